// round 7
// baseline (speedup 1.0000x reference)
#include <cuda_runtime.h>
#include <cuda_bf16.h>
#include <cuda_fp16.h>
#include <cstdint>

#define DMODEL 1024
#define BATCH  4
#define SEQ    2048
#define HEADS  16
#define HDIM   64
#define MROWS  (BATCH*SEQ)   // 8192

// ---------------- device scratch (allocation-free rule) ----------------
__device__ __half g_qhf[(size_t)MROWS * DMODEL];  // [B,H,T,hd] Q hi, pre-scaled 0.125
__device__ __half g_qlf[(size_t)MROWS * DMODEL];  // Q lo residual
__device__ __half g_k16[(size_t)MROWS * DMODEL];  // K single fp16
__device__ __half g_v16[(size_t)MROWS * DMODEL];  // V single fp16
__device__ __nv_bfloat16 g_ahi[(size_t)MROWS * DMODEL];  // [B,T,H*hd]
__device__ __nv_bfloat16 g_alo[(size_t)MROWS * DMODEL];
__device__ __nv_bfloat16 g_xhi[(size_t)MROWS * DMODEL];
__device__ __nv_bfloat16 g_xlo[(size_t)MROWS * DMODEL];
__device__ __nv_bfloat16 g_whi[4][(size_t)DMODEL * DMODEL];
__device__ __nv_bfloat16 g_wlo[4][(size_t)DMODEL * DMODEL];

// ---------------- portable PTX helpers (compute_80+) ----------------
__device__ __forceinline__ uint32_t smem_u32(const void* p) {
    uint32_t a;
    asm("{ .reg .u64 t; cvta.to.shared.u64 t, %1; cvt.u32.u64 %0, t; }"
        : "=r"(a) : "l"(p));
    return a;
}
#define CP_ASYNC16(dst, src) \
    asm volatile("cp.async.cg.shared.global [%0], [%1], 16;" \
                 :: "r"(dst), "l"(src) : "memory")
#define CP_COMMIT() asm volatile("cp.async.commit_group;" ::: "memory")
#define CP_WAIT0()  asm volatile("cp.async.wait_group 0;" ::: "memory")
#define CP_WAIT1()  asm volatile("cp.async.wait_group 1;" ::: "memory")

__device__ __forceinline__ void ldmx4(uint32_t* r, uint32_t addr) {
    asm volatile("ldmatrix.sync.aligned.m8n8.x4.shared.b16 {%0,%1,%2,%3}, [%4];"
                 : "=r"(r[0]), "=r"(r[1]), "=r"(r[2]), "=r"(r[3]) : "r"(addr));
}
__device__ __forceinline__ void ldmx2(uint32_t* r, uint32_t addr) {
    asm volatile("ldmatrix.sync.aligned.m8n8.x2.shared.b16 {%0,%1}, [%2];"
                 : "=r"(r[0]), "=r"(r[1]) : "r"(addr));
}
__device__ __forceinline__ void ldmx4t(uint32_t* r, uint32_t addr) {
    asm volatile("ldmatrix.sync.aligned.m8n8.x4.trans.shared.b16 {%0,%1,%2,%3}, [%4];"
                 : "=r"(r[0]), "=r"(r[1]), "=r"(r[2]), "=r"(r[3]) : "r"(addr));
}
__device__ __forceinline__ void mma_bf16(float* c, const uint32_t* a, const uint32_t* b) {
    asm volatile(
        "mma.sync.aligned.m16n8k16.row.col.f32.bf16.bf16.f32 "
        "{%0,%1,%2,%3}, {%4,%5,%6,%7}, {%8,%9}, {%0,%1,%2,%3};"
        : "+f"(c[0]), "+f"(c[1]), "+f"(c[2]), "+f"(c[3])
        : "r"(a[0]), "r"(a[1]), "r"(a[2]), "r"(a[3]), "r"(b[0]), "r"(b[1]));
}
__device__ __forceinline__ void mma_f16(float* c, const uint32_t* a, const uint32_t* b) {
    asm volatile(
        "mma.sync.aligned.m16n8k16.row.col.f32.f16.f16.f32 "
        "{%0,%1,%2,%3}, {%4,%5,%6,%7}, {%8,%9}, {%0,%1,%2,%3};"
        : "+f"(c[0]), "+f"(c[1]), "+f"(c[2]), "+f"(c[3])
        : "r"(a[0]), "r"(a[1]), "r"(a[2]), "r"(a[3]), "r"(b[0]), "r"(b[1]));
}
__device__ __forceinline__ uint32_t pk_bf16(float lo, float hi) {
    uint32_t d;
    asm("cvt.rn.bf16x2.f32 %0, %1, %2;" : "=r"(d) : "f"(hi), "f"(lo));
    return d;
}
__device__ __forceinline__ uint32_t pk_f16(float lo, float hi) {
    __half2 h = __floats2half2_rn(lo, hi);
    return *(uint32_t*)&h;
}
__device__ __forceinline__ float bf16_rnd(float v, float& res) {
    __nv_bfloat16 h = __float2bfloat16(v);
    float hf = __bfloat162float(h);
    res = v - hf;
    return hf;
}
__device__ __forceinline__ float f16_rnd(float v, float& res) {
    float hf = __half2float(__float2half_rn(v));
    res = v - hf;
    return hf;
}
// FFMA-only 2^y (clamped at -126); rel err ~1e-6
__device__ __forceinline__ float exp2p(float y) {
    y = fmaxf(y, -126.0f);
    float fl = floorf(y);
    float f  = y - fl;
    float p  = 1.5252734e-05f;
    p = fmaf(p, f, 1.5403530e-04f);
    p = fmaf(p, f, 1.3333558e-03f);
    p = fmaf(p, f, 9.6181291e-03f);
    p = fmaf(p, f, 5.5504109e-02f);
    p = fmaf(p, f, 2.4022651e-01f);
    p = fmaf(p, f, 6.9314718e-01f);
    p = fmaf(p, f, 1.0f);
    return p * __int_as_float(((int)fl + 127) << 23);
}
#define LOG2E 1.4426950408889634f

// ---------------- fp32 -> bf16 hi/lo split ----------------
__device__ __forceinline__ void cvt_body(
    const float4* __restrict__ in, uint2* __restrict__ hi,
    uint2* __restrict__ lo, int n4)
{
    int i = blockIdx.x * 256 + threadIdx.x;
    if (i >= n4) return;
    float4 v = in[i];
    __nv_bfloat16 h[4], l[4];
    float f[4] = {v.x, v.y, v.z, v.w};
    #pragma unroll
    for (int j = 0; j < 4; ++j) {
        h[j] = __float2bfloat16(f[j]);
        l[j] = __float2bfloat16(f[j] - __bfloat162float(h[j]));
    }
    hi[i] = *(uint2*)h;
    lo[i] = *(uint2*)l;
}
__global__ __launch_bounds__(256) void cvt_x(
    const float4* __restrict__ in, uint2* __restrict__ hi,
    uint2* __restrict__ lo, int n4)
{
    cvt_body(in, hi, lo, n4);
}
// fused: all 4 weight matrices, blockIdx.y selects
__global__ __launch_bounds__(256) void cvt_w(
    const float4* __restrict__ w0, const float4* __restrict__ w1,
    const float4* __restrict__ w2, const float4* __restrict__ w3, int n4)
{
    const int y = blockIdx.y;
    const float4* src = (y == 0) ? w0 : (y == 1) ? w1 : (y == 2) ? w2 : w3;
    uint2* hi = (uint2*)(&g_whi[0][0] + (size_t)y * DMODEL * DMODEL);
    uint2* lo = (uint2*)(&g_wlo[0][0] + (size_t)y * DMODEL * DMODEL);
    cvt_body(src, hi, lo, n4);
}

// ---------------------------------------------------------------------------
// mma.sync bf16x3 GEMM core.
// mode 1: fp16 hi/lo scatter to [B,H,T,hd] (Q), with scale
// mode 2: fp32 + bias, row-major (output projection)
// mode 3: single fp16 scatter to [B,H,T,hd] (K, V)
// ---------------------------------------------------------------------------
#define PITCH   40
#define TILE_B  (128 * PITCH * 2)
#define STAGE_B (4 * TILE_B)
#define GEMM_SMEM (2 * STAGE_B)

__device__ __forceinline__ void gemm_body(
    const __nv_bfloat16* __restrict__ Ah, const __nv_bfloat16* __restrict__ Al,
    const __nv_bfloat16* __restrict__ Bh, const __nv_bfloat16* __restrict__ Bl,
    float* __restrict__ Cf, const float* __restrict__ bias,
    __half* __restrict__ H1, __half* __restrict__ H2,
    float scale, int mode, char* smem)
{
    const uint32_t sb = smem_u32(smem);
    const int tid  = threadIdx.x;
    const int wid  = tid >> 5, lane = tid & 31;
    const int wm   = wid & 1, wn = wid >> 1;
    const int m0   = blockIdx.y << 7;
    const int n0   = blockIdx.x << 7;

    const __nv_bfloat16* srcs[4] = {Ah, Al, Bh, Bl};

    auto prefetch = [&](int c, int st) {
        const int kk = c << 5;
        #pragma unroll
        for (int i = 0; i < 8; ++i) {
            int idx  = tid + i * 256;
            int tile = idx >> 9;
            int loc  = idx & 511;
            int r    = loc >> 2;
            int seg  = loc & 3;
            int rowb = (tile < 2) ? m0 : n0;
            const __nv_bfloat16* src =
                srcs[tile] + (size_t)(rowb + r) * DMODEL + kk + seg * 8;
            uint32_t dst = sb + st * STAGE_B + tile * TILE_B + r * (PITCH*2) + seg * 16;
            CP_ASYNC16(dst, src);
        }
        CP_COMMIT();
    };

    float acc[4][4][4] = {};
    prefetch(0, 0);

    for (int c = 0; c < 32; ++c) {
        const int st = c & 1;
        CP_WAIT0();
        __syncthreads();
        if (c + 1 < 32) prefetch(c + 1, st ^ 1);

        const uint32_t sA = sb + st * STAGE_B;
        const uint32_t sB = sA + 2 * TILE_B;

        #pragma unroll
        for (int ks = 0; ks < 2; ++ks) {
            uint32_t ah[4][4], al[4][4], bh[4][2], bl[4][2];
            const uint32_t kb = ks * 32;
            #pragma unroll
            for (int mi = 0; mi < 4; ++mi) {
                uint32_t off = (uint32_t)(wm*64 + mi*16 + (lane & 15)) * (PITCH*2)
                             + kb + (lane >> 4) * 16;
                ldmx4(ah[mi], sA + off);
                ldmx4(al[mi], sA + TILE_B + off);
            }
            #pragma unroll
            for (int ni = 0; ni < 4; ++ni) {
                int l16 = lane & 15;
                uint32_t off = (uint32_t)(wn*32 + ni*8 + (l16 & 7)) * (PITCH*2)
                             + kb + (l16 >> 3) * 16;
                ldmx2(bh[ni], sB + off);
                ldmx2(bl[ni], sB + TILE_B + off);
            }
            #pragma unroll
            for (int mi = 0; mi < 4; ++mi)
                #pragma unroll
                for (int ni = 0; ni < 4; ++ni) {
                    mma_bf16(acc[mi][ni], ah[mi], bh[ni]);
                    mma_bf16(acc[mi][ni], ah[mi], bl[ni]);
                    mma_bf16(acc[mi][ni], al[mi], bh[ni]);
                }
        }
        __syncthreads();
    }

    const int r0 = wm * 64 + (lane >> 2);
    const int cbase = wn * 32 + (lane & 3) * 2;
    #pragma unroll
    for (int mi = 0; mi < 4; ++mi) {
        #pragma unroll
        for (int ni = 0; ni < 4; ++ni) {
            int n = n0 + cbase + ni * 8;
            #pragma unroll
            for (int half = 0; half < 2; ++half) {
                int m = m0 + r0 + mi * 16 + half * 8;
                float v0 = acc[mi][ni][half*2+0];
                float v1 = acc[mi][ni][half*2+1];
                if (mode == 2) {
                    float2 bv = *(const float2*)(bias + n);
                    *(float2*)(Cf + (size_t)m*DMODEL + n) = make_float2(v0 + bv.x, v1 + bv.y);
                } else {
                    int bb = m >> 11, t = m & (SEQ - 1);
                    int h = n >> 6, hd = n & 63;
                    size_t off = (((size_t)bb*HEADS + h)*SEQ + t)*HDIM + hd;
                    float s0 = v0 * scale, s1 = v1 * scale;
                    if (mode == 1) {
                        float r0f, r1f;
                        float h0 = f16_rnd(s0, r0f);
                        float h1 = f16_rnd(s1, r1f);
                        *(uint32_t*)(H1 + off) = pk_f16(h0, h1);
                        *(uint32_t*)(H2 + off) = pk_f16(r0f, r1f);
                    } else {
                        *(uint32_t*)(H1 + off) = pk_f16(s0, s1);
                    }
                }
            }
        }
    }
}

// Fused Q/K/V projection: blockIdx.z = 0/1/2
__global__ __launch_bounds__(256, 1) void gemm_qkv(
    const __nv_bfloat16* __restrict__ Ah, const __nv_bfloat16* __restrict__ Al)
{
    extern __shared__ char smem[];
    const int z = blockIdx.z;
    const size_t WS = (size_t)DMODEL * DMODEL;
    const __nv_bfloat16* Bh = &g_whi[0][0] + (size_t)z * WS;
    const __nv_bfloat16* Bl = &g_wlo[0][0] + (size_t)z * WS;
    if (z == 0)
        gemm_body(Ah, Al, Bh, Bl, nullptr, nullptr, g_qhf, g_qlf, 0.125f, 1, smem);
    else if (z == 1)
        gemm_body(Ah, Al, Bh, Bl, nullptr, nullptr, g_k16, nullptr, 1.0f, 3, smem);
    else
        gemm_body(Ah, Al, Bh, Bl, nullptr, nullptr, g_v16, nullptr, 1.0f, 3, smem);
}

// Output projection (fp32 + bias)
__global__ __launch_bounds__(256, 1) void gemm_out(
    const __nv_bfloat16* __restrict__ Ah, const __nv_bfloat16* __restrict__ Al,
    float* __restrict__ Cf, const float* __restrict__ bias)
{
    extern __shared__ char smem[];
    const size_t WS = (size_t)DMODEL * DMODEL;
    gemm_body(Ah, Al, &g_whi[0][0] + 3 * WS, &g_wlo[0][0] + 3 * WS,
              Cf, bias, nullptr, nullptr, 1.0f, 2, smem);
}

// ---------------------------------------------------------------------------
// fp16 tensor-core flash attention, shift-free softmax.
// QK^T: (qh+ql) * k16   (2 passes, only K rounded)
// PV:   (ph+pl) * v16   (2 passes, only V rounded)
// ---------------------------------------------------------------------------
#define APB       144
#define AQ_BYTES  (128 * APB)          // 18432
#define AKV_BYTES (64 * APB)           // 9216
#define ASTAGE    (2 * AKV_BYTES)      // 18432 (K + V)
#define ATTN_SMEM (2 * AQ_BYTES + 2 * ASTAGE)  // 73728

__global__ __launch_bounds__(256, 1) void attn_mma()
{
    extern __shared__ char sm[];
    const uint32_t sb = smem_u32(sm);
    const int tid = threadIdx.x;
    const int wid = tid >> 5, lane = tid & 31;
    const int bh  = blockIdx.y;
    const int q0  = blockIdx.x << 7;

    const uint32_t sQh = sb, sQl = sb + AQ_BYTES;
    const uint32_t sKV = sb + 2 * AQ_BYTES;

    const size_t qbase = ((size_t)bh * SEQ + q0) * HDIM;
    #pragma unroll
    for (int i = 0; i < 8; ++i) {
        int idx = tid + i * 256;
        int arr = idx >> 10, loc = idx & 1023, row = loc >> 3, seg = loc & 7;
        const __half* src = (arr ? g_qlf : g_qhf) + qbase + (size_t)row * HDIM + seg * 8;
        uint32_t dst = (arr ? sQl : sQh) + row * APB + seg * 16;
        CP_ASYNC16(dst, src);
    }
    auto prefetch_kv = [&](int kt, int st) {
        const size_t kb = ((size_t)bh * SEQ + kt * 64) * HDIM;
        #pragma unroll
        for (int i = 0; i < 4; ++i) {
            int idx = tid + i * 256;
            int arr = idx >> 9, loc = idx & 511, row = loc >> 3, seg = loc & 7;
            const __half* src = (arr ? g_v16 : g_k16) + kb + (size_t)row * HDIM + seg * 8;
            uint32_t dst = sKV + st * ASTAGE + arr * AKV_BYTES + row * APB + seg * 16;
            CP_ASYNC16(dst, src);
        }
    };
    prefetch_kv(0, 0); CP_COMMIT();
    prefetch_kv(1, 1); CP_COMMIT();

    CP_WAIT1();
    __syncthreads();
    uint32_t qh[4][4], ql[4][4];
    #pragma unroll
    for (int ks = 0; ks < 4; ++ks) {
        uint32_t off = (uint32_t)(wid*16 + (lane & 15)) * APB + (lane >> 4) * 16 + ks * 32;
        ldmx4(qh[ks], sQh + off);
        ldmx4(ql[ks], sQl + off);
    }

    float o[8][4] = {};
    float li[2] = {};

    for (int kt = 0; kt < SEQ / 64; ++kt) {
        const int st = kt & 1;
        CP_WAIT1();
        __syncthreads();
        const uint32_t sK = sKV + st * ASTAGE;
        const uint32_t sV = sK + AKV_BYTES;

        // ---- S = Q K^T  (Q split, K single)
        float s[8][4] = {};
        #pragma unroll
        for (int ks = 0; ks < 4; ++ks) {
            #pragma unroll
            for (int np = 0; np < 4; ++np) {
                uint32_t k4[4];
                uint32_t key  = np*16 + ((lane >> 4) << 3) + (lane & 7);
                uint32_t koff = ks*32 + ((lane >> 3) & 1) * 16;
                uint32_t a = key * APB + koff;
                ldmx4(k4, sK + a);
                mma_f16(s[2*np],   qh[ks], k4);
                mma_f16(s[2*np],   ql[ks], k4);
                mma_f16(s[2*np+1], qh[ks], k4 + 2);
                mma_f16(s[2*np+1], ql[ks], k4 + 2);
            }
        }

        // ---- shift-free softmax: P = exp(S); local row sums
        {
            float l0 = 0.f, l1 = 0.f;
            #pragma unroll
            for (int nt = 0; nt < 8; ++nt) {
                float e0 = exp2p(s[nt][0] * LOG2E);
                float e1 = exp2p(s[nt][1] * LOG2E);
                float e2 = exp2p(s[nt][2] * LOG2E);
                float e3 = exp2p(s[nt][3] * LOG2E);
                s[nt][0] = e0; s[nt][1] = e1;
                s[nt][2] = e2; s[nt][3] = e3;
                l0 += e0 + e1;
                l1 += e2 + e3;
            }
            li[0] += l0; li[1] += l1;
        }

        // ---- O += P V  (P split, V single)
        #pragma unroll
        for (int ks = 0; ks < 4; ++ks) {
            uint32_t pah[4], pal[4];
            #pragma unroll
            for (int half = 0; half < 2; ++half) {
                const float* sv = s[2*ks + half];
                float r0f, r1f, r2f, r3f;
                float h0 = f16_rnd(sv[0], r0f);
                float h1 = f16_rnd(sv[1], r1f);
                float h2 = f16_rnd(sv[2], r2f);
                float h3 = f16_rnd(sv[3], r3f);
                pah[2*half]   = pk_f16(h0, h1);
                pah[2*half+1] = pk_f16(h2, h3);
                pal[2*half]   = pk_f16(r0f, r1f);
                pal[2*half+1] = pk_f16(r2f, r3f);
            }
            #pragma unroll
            for (int njp = 0; njp < 4; ++njp) {
                uint32_t v4[4];
                uint32_t key  = ks*16 + ((lane >> 3) & 1) * 8 + (lane & 7);
                uint32_t colb = (2*njp + (lane >> 4)) * 16;
                uint32_t a = key * APB + colb;
                ldmx4t(v4, sV + a);
                mma_f16(o[2*njp],   pah, v4);
                mma_f16(o[2*njp],   pal, v4);
                mma_f16(o[2*njp+1], pah, v4 + 2);
                mma_f16(o[2*njp+1], pal, v4 + 2);
            }
        }

        __syncthreads();
        if (kt + 2 < SEQ / 64) prefetch_kv(kt + 2, st);
        CP_COMMIT();
    }

    // ---- deferred row-sum reduce + epilogue (bf16 hi/lo for out-proj)
    #pragma unroll
    for (int rr = 0; rr < 2; ++rr) {
        li[rr] += __shfl_xor_sync(0xffffffffu, li[rr], 1);
        li[rr] += __shfl_xor_sync(0xffffffffu, li[rr], 2);
    }
    const int b = bh >> 4, h = bh & 15;
    #pragma unroll
    for (int rr = 0; rr < 2; ++rr) {
        float inv = 1.0f / (li[rr] + 1e-8f);
        int t = q0 + wid*16 + (lane >> 2) + rr*8;
        size_t base = ((size_t)b * SEQ + t) * DMODEL + h * HDIM;
        #pragma unroll
        for (int nt = 0; nt < 8; ++nt) {
            int col = nt*8 + (lane & 3)*2;
            float v0 = o[nt][2*rr]   * inv;
            float v1 = o[nt][2*rr+1] * inv;
            float r0f, r1f;
            float h0 = bf16_rnd(v0, r0f);
            float h1 = bf16_rnd(v1, r1f);
            *(uint32_t*)(g_ahi + base + col) = pk_bf16(h0, h1);
            *(uint32_t*)(g_alo + base + col) = pk_bf16(r0f, r1f);
        }
    }
}

// ---------------------------------------------------------------------------
extern "C" void kernel_launch(void* const* d_in, const int* in_sizes, int n_in,
                              void* d_out, int out_size)
{
    const float* x  = (const float*)d_in[0];
    const float* Wq = (const float*)d_in[1];
    const float* Wk = (const float*)d_in[2];
    const float* Wv = (const float*)d_in[3];
    const float* Wo = (const float*)d_in[4];
    const float* bo = (const float*)d_in[5];

    __nv_bfloat16 *xhi, *xlo, *ahi, *alo;
    cudaGetSymbolAddress((void**)&xhi, g_xhi);
    cudaGetSymbolAddress((void**)&xlo, g_xlo);
    cudaGetSymbolAddress((void**)&ahi, g_ahi);
    cudaGetSymbolAddress((void**)&alo, g_alo);

    const int NX4 = MROWS * DMODEL / 4;
    const int NW4 = DMODEL * DMODEL / 4;

    cvt_x<<<(NX4 + 255) / 256, 256>>>((const float4*)x, (uint2*)xhi, (uint2*)xlo, NX4);
    cvt_w<<<dim3((NW4 + 255) / 256, 4), 256>>>(
        (const float4*)Wq, (const float4*)Wk, (const float4*)Wv, (const float4*)Wo, NW4);

    cudaFuncSetAttribute(gemm_qkv, cudaFuncAttributeMaxDynamicSharedMemorySize, GEMM_SMEM);
    cudaFuncSetAttribute(gemm_out, cudaFuncAttributeMaxDynamicSharedMemorySize, GEMM_SMEM);
    dim3 gq(DMODEL / 128, MROWS / 128, 3);
    gemm_qkv<<<gq, 256, GEMM_SMEM>>>(xhi, xlo);

    cudaFuncSetAttribute(attn_mma, cudaFuncAttributeMaxDynamicSharedMemorySize, ATTN_SMEM);
    attn_mma<<<dim3(SEQ / 128, BATCH * HEADS), 256, ATTN_SMEM>>>();

    dim3 gg(DMODEL / 128, MROWS / 128);
    gemm_out<<<gg, 256, GEMM_SMEM>>>(ahi, alo, (float*)d_out, bo);
}

// round 8
// speedup vs baseline: 1.6460x; 1.6460x over previous
#include <cuda_runtime.h>
#include <cuda_bf16.h>
#include <cuda_fp16.h>
#include <cstdint>

#define DMODEL 1024
#define BATCH  4
#define SEQ    2048
#define HEADS  16
#define HDIM   64
#define MROWS  (BATCH*SEQ)   // 8192

// ---------------- device scratch (allocation-free rule) ----------------
__device__ __half g_qhf[(size_t)MROWS * DMODEL];  // [B,H,T,hd] Q hi, pre-scaled 0.125
__device__ __half g_qlf[(size_t)MROWS * DMODEL];  // Q lo residual
__device__ __half g_k16[(size_t)MROWS * DMODEL];  // K single fp16
__device__ __half g_v16[(size_t)MROWS * DMODEL];  // V single fp16
__device__ __nv_bfloat16 g_ahi[(size_t)MROWS * DMODEL];  // [B,T,H*hd]
__device__ __nv_bfloat16 g_alo[(size_t)MROWS * DMODEL];
__device__ __nv_bfloat16 g_xhi[(size_t)MROWS * DMODEL];
__device__ __nv_bfloat16 g_xlo[(size_t)MROWS * DMODEL];
__device__ __nv_bfloat16 g_whi[4][(size_t)DMODEL * DMODEL];
__device__ __nv_bfloat16 g_wlo[4][(size_t)DMODEL * DMODEL];

// ---------------- portable PTX helpers (compute_80+) ----------------
__device__ __forceinline__ uint32_t smem_u32(const void* p) {
    uint32_t a;
    asm("{ .reg .u64 t; cvta.to.shared.u64 t, %1; cvt.u32.u64 %0, t; }"
        : "=r"(a) : "l"(p));
    return a;
}
#define CP_ASYNC16(dst, src) \
    asm volatile("cp.async.cg.shared.global [%0], [%1], 16;" \
                 :: "r"(dst), "l"(src) : "memory")
#define CP_COMMIT() asm volatile("cp.async.commit_group;" ::: "memory")
#define CP_WAIT0()  asm volatile("cp.async.wait_group 0;" ::: "memory")
#define CP_WAIT1()  asm volatile("cp.async.wait_group 1;" ::: "memory")

__device__ __forceinline__ void ldmx4(uint32_t* r, uint32_t addr) {
    asm volatile("ldmatrix.sync.aligned.m8n8.x4.shared.b16 {%0,%1,%2,%3}, [%4];"
                 : "=r"(r[0]), "=r"(r[1]), "=r"(r[2]), "=r"(r[3]) : "r"(addr));
}
__device__ __forceinline__ void ldmx2(uint32_t* r, uint32_t addr) {
    asm volatile("ldmatrix.sync.aligned.m8n8.x2.shared.b16 {%0,%1}, [%2];"
                 : "=r"(r[0]), "=r"(r[1]) : "r"(addr));
}
__device__ __forceinline__ void ldmx4t(uint32_t* r, uint32_t addr) {
    asm volatile("ldmatrix.sync.aligned.m8n8.x4.trans.shared.b16 {%0,%1,%2,%3}, [%4];"
                 : "=r"(r[0]), "=r"(r[1]), "=r"(r[2]), "=r"(r[3]) : "r"(addr));
}
__device__ __forceinline__ void mma_bf16(float* c, const uint32_t* a, const uint32_t* b) {
    asm volatile(
        "mma.sync.aligned.m16n8k16.row.col.f32.bf16.bf16.f32 "
        "{%0,%1,%2,%3}, {%4,%5,%6,%7}, {%8,%9}, {%0,%1,%2,%3};"
        : "+f"(c[0]), "+f"(c[1]), "+f"(c[2]), "+f"(c[3])
        : "r"(a[0]), "r"(a[1]), "r"(a[2]), "r"(a[3]), "r"(b[0]), "r"(b[1]));
}
__device__ __forceinline__ void mma_f16(float* c, const uint32_t* a, const uint32_t* b) {
    asm volatile(
        "mma.sync.aligned.m16n8k16.row.col.f32.f16.f16.f32 "
        "{%0,%1,%2,%3}, {%4,%5,%6,%7}, {%8,%9}, {%0,%1,%2,%3};"
        : "+f"(c[0]), "+f"(c[1]), "+f"(c[2]), "+f"(c[3])
        : "r"(a[0]), "r"(a[1]), "r"(a[2]), "r"(a[3]), "r"(b[0]), "r"(b[1]));
}
__device__ __forceinline__ uint32_t pk_bf16(float lo, float hi) {
    uint32_t d;
    asm("cvt.rn.bf16x2.f32 %0, %1, %2;" : "=r"(d) : "f"(hi), "f"(lo));
    return d;
}
__device__ __forceinline__ uint32_t pk_f16(float lo, float hi) {
    __half2 h = __floats2half2_rn(lo, hi);
    return *(uint32_t*)&h;
}
__device__ __forceinline__ float bf16_rnd(float v, float& res) {
    __nv_bfloat16 h = __float2bfloat16(v);
    float hf = __bfloat162float(h);
    res = v - hf;
    return hf;
}
__device__ __forceinline__ float f16_rnd(float v, float& res) {
    float hf = __half2float(__float2half_rn(v));
    res = v - hf;
    return hf;
}
// FFMA-only 2^y (clamped at -126); rel err ~1e-6
__device__ __forceinline__ float exp2p(float y) {
    y = fmaxf(y, -126.0f);
    float fl = floorf(y);
    float f  = y - fl;
    float p  = 1.5252734e-05f;
    p = fmaf(p, f, 1.5403530e-04f);
    p = fmaf(p, f, 1.3333558e-03f);
    p = fmaf(p, f, 9.6181291e-03f);
    p = fmaf(p, f, 5.5504109e-02f);
    p = fmaf(p, f, 2.4022651e-01f);
    p = fmaf(p, f, 6.9314718e-01f);
    p = fmaf(p, f, 1.0f);
    return p * __int_as_float(((int)fl + 127) << 23);
}
#define LOG2E 1.4426950408889634f

// ---------------- fp32 -> bf16 hi/lo split ----------------
__device__ __forceinline__ void cvt_body(
    const float4* __restrict__ in, uint2* __restrict__ hi,
    uint2* __restrict__ lo, int n4)
{
    int i = blockIdx.x * 256 + threadIdx.x;
    if (i >= n4) return;
    float4 v = in[i];
    __nv_bfloat16 h[4], l[4];
    float f[4] = {v.x, v.y, v.z, v.w};
    #pragma unroll
    for (int j = 0; j < 4; ++j) {
        h[j] = __float2bfloat16(f[j]);
        l[j] = __float2bfloat16(f[j] - __bfloat162float(h[j]));
    }
    hi[i] = *(uint2*)h;
    lo[i] = *(uint2*)l;
}
__global__ __launch_bounds__(256) void cvt_x(
    const float4* __restrict__ in, uint2* __restrict__ hi,
    uint2* __restrict__ lo, int n4)
{
    cvt_body(in, hi, lo, n4);
}
__global__ __launch_bounds__(256) void cvt_w(
    const float4* __restrict__ w0, const float4* __restrict__ w1,
    const float4* __restrict__ w2, const float4* __restrict__ w3, int n4)
{
    const int y = blockIdx.y;
    const float4* src = (y == 0) ? w0 : (y == 1) ? w1 : (y == 2) ? w2 : w3;
    uint2* hi = (uint2*)(&g_whi[0][0] + (size_t)y * DMODEL * DMODEL);
    uint2* lo = (uint2*)(&g_wlo[0][0] + (size_t)y * DMODEL * DMODEL);
    cvt_body(src, hi, lo, n4);
}

// ---------------------------------------------------------------------------
// mma.sync bf16x3 GEMM core — SINGLE instantiation, runtime mode dispatch.
// mode 1: fp16 hi/lo scatter to [B,H,T,hd] (Q), with scale
// mode 2: fp32 + bias, row-major (output projection)
// mode 3: single fp16 scatter to [B,H,T,hd] (K, V)
// ---------------------------------------------------------------------------
#define PITCH   40
#define TILE_B  (128 * PITCH * 2)
#define STAGE_B (4 * TILE_B)
#define GEMM_SMEM (2 * STAGE_B)

__device__ void gemm_body(
    const __nv_bfloat16* __restrict__ Ah, const __nv_bfloat16* __restrict__ Al,
    const __nv_bfloat16* __restrict__ Bh, const __nv_bfloat16* __restrict__ Bl,
    float* __restrict__ Cf, const float* __restrict__ bias,
    __half* __restrict__ H1, __half* __restrict__ H2,
    float scale, int mode, char* smem)
{
    const uint32_t sb = smem_u32(smem);
    const int tid  = threadIdx.x;
    const int wid  = tid >> 5, lane = tid & 31;
    const int wm   = wid & 1, wn = wid >> 1;
    const int m0   = blockIdx.y << 7;
    const int n0   = blockIdx.x << 7;

    const __nv_bfloat16* srcs[4] = {Ah, Al, Bh, Bl};

    auto prefetch = [&](int c, int st) {
        const int kk = c << 5;
        #pragma unroll
        for (int i = 0; i < 8; ++i) {
            int idx  = tid + i * 256;
            int tile = idx >> 9;
            int loc  = idx & 511;
            int r    = loc >> 2;
            int seg  = loc & 3;
            int rowb = (tile < 2) ? m0 : n0;
            const __nv_bfloat16* src =
                srcs[tile] + (size_t)(rowb + r) * DMODEL + kk + seg * 8;
            uint32_t dst = sb + st * STAGE_B + tile * TILE_B + r * (PITCH*2) + seg * 16;
            CP_ASYNC16(dst, src);
        }
        CP_COMMIT();
    };

    float acc[4][4][4] = {};
    prefetch(0, 0);

    for (int c = 0; c < 32; ++c) {
        const int st = c & 1;
        CP_WAIT0();
        __syncthreads();
        if (c + 1 < 32) prefetch(c + 1, st ^ 1);

        const uint32_t sA = sb + st * STAGE_B;
        const uint32_t sB = sA + 2 * TILE_B;

        #pragma unroll
        for (int ks = 0; ks < 2; ++ks) {
            uint32_t ah[4][4], al[4][4], bh[4][2], bl[4][2];
            const uint32_t kb = ks * 32;
            #pragma unroll
            for (int mi = 0; mi < 4; ++mi) {
                uint32_t off = (uint32_t)(wm*64 + mi*16 + (lane & 15)) * (PITCH*2)
                             + kb + (lane >> 4) * 16;
                ldmx4(ah[mi], sA + off);
                ldmx4(al[mi], sA + TILE_B + off);
            }
            #pragma unroll
            for (int ni = 0; ni < 4; ++ni) {
                int l16 = lane & 15;
                uint32_t off = (uint32_t)(wn*32 + ni*8 + (l16 & 7)) * (PITCH*2)
                             + kb + (l16 >> 3) * 16;
                ldmx2(bh[ni], sB + off);
                ldmx2(bl[ni], sB + TILE_B + off);
            }
            #pragma unroll
            for (int mi = 0; mi < 4; ++mi)
                #pragma unroll
                for (int ni = 0; ni < 4; ++ni) {
                    mma_bf16(acc[mi][ni], ah[mi], bh[ni]);
                    mma_bf16(acc[mi][ni], ah[mi], bl[ni]);
                    mma_bf16(acc[mi][ni], al[mi], bh[ni]);
                }
        }
        __syncthreads();
    }

    const int r0 = wm * 64 + (lane >> 2);
    const int cbase = wn * 32 + (lane & 3) * 2;
    #pragma unroll
    for (int mi = 0; mi < 4; ++mi) {
        #pragma unroll
        for (int ni = 0; ni < 4; ++ni) {
            int n = n0 + cbase + ni * 8;
            #pragma unroll
            for (int half = 0; half < 2; ++half) {
                int m = m0 + r0 + mi * 16 + half * 8;
                float v0 = acc[mi][ni][half*2+0];
                float v1 = acc[mi][ni][half*2+1];
                if (mode == 2) {
                    float2 bv = *(const float2*)(bias + n);
                    *(float2*)(Cf + (size_t)m*DMODEL + n) = make_float2(v0 + bv.x, v1 + bv.y);
                } else {
                    int bb = m >> 11, t = m & (SEQ - 1);
                    int h = n >> 6, hd = n & 63;
                    size_t off = (((size_t)bb*HEADS + h)*SEQ + t)*HDIM + hd;
                    float s0 = v0 * scale, s1 = v1 * scale;
                    if (mode == 1) {
                        float r0f, r1f;
                        float h0 = f16_rnd(s0, r0f);
                        float h1 = f16_rnd(s1, r1f);
                        *(uint32_t*)(H1 + off) = pk_f16(h0, h1);
                        *(uint32_t*)(H2 + off) = pk_f16(r0f, r1f);
                    } else {
                        *(uint32_t*)(H1 + off) = pk_f16(s0, s1);
                    }
                }
            }
        }
    }
}

// Fused Q/K/V projection: blockIdx.z = 0/1/2 — runtime params, ONE body.
__global__ __launch_bounds__(256, 1) void gemm_qkv(
    const __nv_bfloat16* __restrict__ Ah, const __nv_bfloat16* __restrict__ Al)
{
    extern __shared__ char smem[];
    const int z = blockIdx.z;
    const size_t WS = (size_t)DMODEL * DMODEL;
    const __nv_bfloat16* Bh = &g_whi[0][0] + (size_t)z * WS;
    const __nv_bfloat16* Bl = &g_wlo[0][0] + (size_t)z * WS;
    __half* H1 = (z == 0) ? g_qhf : (z == 1) ? g_k16 : g_v16;
    __half* H2 = g_qlf;                                  // used only when mode==1
    float scale = (z == 0) ? 0.125f : 1.0f;
    int mode = (z == 0) ? 1 : 3;
    gemm_body(Ah, Al, Bh, Bl, nullptr, nullptr, H1, H2, scale, mode, smem);
}

// Output projection (fp32 + bias)
__global__ __launch_bounds__(256, 1) void gemm_out(
    const __nv_bfloat16* __restrict__ Ah, const __nv_bfloat16* __restrict__ Al,
    float* __restrict__ Cf, const float* __restrict__ bias)
{
    extern __shared__ char smem[];
    const size_t WS = (size_t)DMODEL * DMODEL;
    gemm_body(Ah, Al, &g_whi[0][0] + 3 * WS, &g_wlo[0][0] + 3 * WS,
              Cf, bias, nullptr, nullptr, 1.0f, 2, smem);
}

// ---------------------------------------------------------------------------
// fp16 tensor-core flash attention, shift-free softmax.
// QK^T: (qh+ql) * k16   (2 passes, only K rounded)
// PV:   p16 * v16       (1 pass; P and V rounded — within error budget)
// ---------------------------------------------------------------------------
#define APB       144
#define AQ_BYTES  (128 * APB)          // 18432
#define AKV_BYTES (64 * APB)           // 9216
#define ASTAGE    (2 * AKV_BYTES)      // 18432 (K + V)
#define ATTN_SMEM (2 * AQ_BYTES + 2 * ASTAGE)  // 73728

__global__ __launch_bounds__(256, 1) void attn_mma()
{
    extern __shared__ char sm[];
    const uint32_t sb = smem_u32(sm);
    const int tid = threadIdx.x;
    const int wid = tid >> 5, lane = tid & 31;
    const int bh  = blockIdx.y;
    const int q0  = blockIdx.x << 7;

    const uint32_t sQh = sb, sQl = sb + AQ_BYTES;
    const uint32_t sKV = sb + 2 * AQ_BYTES;

    const size_t qbase = ((size_t)bh * SEQ + q0) * HDIM;
    #pragma unroll
    for (int i = 0; i < 8; ++i) {
        int idx = tid + i * 256;
        int arr = idx >> 10, loc = idx & 1023, row = loc >> 3, seg = loc & 7;
        const __half* src = (arr ? g_qlf : g_qhf) + qbase + (size_t)row * HDIM + seg * 8;
        uint32_t dst = (arr ? sQl : sQh) + row * APB + seg * 16;
        CP_ASYNC16(dst, src);
    }
    auto prefetch_kv = [&](int kt, int st) {
        const size_t kb = ((size_t)bh * SEQ + kt * 64) * HDIM;
        #pragma unroll
        for (int i = 0; i < 4; ++i) {
            int idx = tid + i * 256;
            int arr = idx >> 9, loc = idx & 511, row = loc >> 3, seg = loc & 7;
            const __half* src = (arr ? g_v16 : g_k16) + kb + (size_t)row * HDIM + seg * 8;
            uint32_t dst = sKV + st * ASTAGE + arr * AKV_BYTES + row * APB + seg * 16;
            CP_ASYNC16(dst, src);
        }
    };
    prefetch_kv(0, 0); CP_COMMIT();
    prefetch_kv(1, 1); CP_COMMIT();

    CP_WAIT1();
    __syncthreads();
    uint32_t qh[4][4], ql[4][4];
    #pragma unroll
    for (int ks = 0; ks < 4; ++ks) {
        uint32_t off = (uint32_t)(wid*16 + (lane & 15)) * APB + (lane >> 4) * 16 + ks * 32;
        ldmx4(qh[ks], sQh + off);
        ldmx4(ql[ks], sQl + off);
    }

    float o[8][4] = {};
    float li[2] = {};

    for (int kt = 0; kt < SEQ / 64; ++kt) {
        const int st = kt & 1;
        CP_WAIT1();
        __syncthreads();
        const uint32_t sK = sKV + st * ASTAGE;
        const uint32_t sV = sK + AKV_BYTES;

        // ---- S = Q K^T  (Q split, K single)
        float s[8][4] = {};
        #pragma unroll
        for (int ks = 0; ks < 4; ++ks) {
            #pragma unroll
            for (int np = 0; np < 4; ++np) {
                uint32_t k4[4];
                uint32_t key  = np*16 + ((lane >> 4) << 3) + (lane & 7);
                uint32_t koff = ks*32 + ((lane >> 3) & 1) * 16;
                uint32_t a = key * APB + koff;
                ldmx4(k4, sK + a);
                mma_f16(s[2*np],   qh[ks], k4);
                mma_f16(s[2*np],   ql[ks], k4);
                mma_f16(s[2*np+1], qh[ks], k4 + 2);
                mma_f16(s[2*np+1], ql[ks], k4 + 2);
            }
        }

        // ---- shift-free softmax: P = exp(S); local row sums
        {
            float l0 = 0.f, l1 = 0.f;
            #pragma unroll
            for (int nt = 0; nt < 8; ++nt) {
                float e0 = exp2p(s[nt][0] * LOG2E);
                float e1 = exp2p(s[nt][1] * LOG2E);
                float e2 = exp2p(s[nt][2] * LOG2E);
                float e3 = exp2p(s[nt][3] * LOG2E);
                s[nt][0] = e0; s[nt][1] = e1;
                s[nt][2] = e2; s[nt][3] = e3;
                l0 += e0 + e1;
                l1 += e2 + e3;
            }
            li[0] += l0; li[1] += l1;
        }

        // ---- O += P V  (single-pass fp16 P, fp16 V)
        #pragma unroll
        for (int ks = 0; ks < 4; ++ks) {
            uint32_t pa[4];
            #pragma unroll
            for (int half = 0; half < 2; ++half) {
                const float* sv = s[2*ks + half];
                pa[2*half]   = pk_f16(sv[0], sv[1]);
                pa[2*half+1] = pk_f16(sv[2], sv[3]);
            }
            #pragma unroll
            for (int njp = 0; njp < 4; ++njp) {
                uint32_t v4[4];
                uint32_t key  = ks*16 + ((lane >> 3) & 1) * 8 + (lane & 7);
                uint32_t colb = (2*njp + (lane >> 4)) * 16;
                uint32_t a = key * APB + colb;
                ldmx4t(v4, sV + a);
                mma_f16(o[2*njp],   pa, v4);
                mma_f16(o[2*njp+1], pa, v4 + 2);
            }
        }

        __syncthreads();
        if (kt + 2 < SEQ / 64) prefetch_kv(kt + 2, st);
        CP_COMMIT();
    }

    // ---- deferred row-sum reduce + epilogue (bf16 hi/lo for out-proj)
    #pragma unroll
    for (int rr = 0; rr < 2; ++rr) {
        li[rr] += __shfl_xor_sync(0xffffffffu, li[rr], 1);
        li[rr] += __shfl_xor_sync(0xffffffffu, li[rr], 2);
    }
    const int b = bh >> 4, h = bh & 15;
    #pragma unroll
    for (int rr = 0; rr < 2; ++rr) {
        float inv = 1.0f / (li[rr] + 1e-8f);
        int t = q0 + wid*16 + (lane >> 2) + rr*8;
        size_t base = ((size_t)b * SEQ + t) * DMODEL + h * HDIM;
        #pragma unroll
        for (int nt = 0; nt < 8; ++nt) {
            int col = nt*8 + (lane & 3)*2;
            float v0 = o[nt][2*rr]   * inv;
            float v1 = o[nt][2*rr+1] * inv;
            float r0f, r1f;
            float h0 = bf16_rnd(v0, r0f);
            float h1 = bf16_rnd(v1, r1f);
            *(uint32_t*)(g_ahi + base + col) = pk_bf16(h0, h1);
            *(uint32_t*)(g_alo + base + col) = pk_bf16(r0f, r1f);
        }
    }
}

// ---------------------------------------------------------------------------
extern "C" void kernel_launch(void* const* d_in, const int* in_sizes, int n_in,
                              void* d_out, int out_size)
{
    const float* x  = (const float*)d_in[0];
    const float* Wq = (const float*)d_in[1];
    const float* Wk = (const float*)d_in[2];
    const float* Wv = (const float*)d_in[3];
    const float* Wo = (const float*)d_in[4];
    const float* bo = (const float*)d_in[5];

    __nv_bfloat16 *xhi, *xlo, *ahi, *alo;
    cudaGetSymbolAddress((void**)&xhi, g_xhi);
    cudaGetSymbolAddress((void**)&xlo, g_xlo);
    cudaGetSymbolAddress((void**)&ahi, g_ahi);
    cudaGetSymbolAddress((void**)&alo, g_alo);

    const int NX4 = MROWS * DMODEL / 4;
    const int NW4 = DMODEL * DMODEL / 4;

    cvt_x<<<(NX4 + 255) / 256, 256>>>((const float4*)x, (uint2*)xhi, (uint2*)xlo, NX4);
    cvt_w<<<dim3((NW4 + 255) / 256, 4), 256>>>(
        (const float4*)Wq, (const float4*)Wk, (const float4*)Wv, (const float4*)Wo, NW4);

    cudaFuncSetAttribute(gemm_qkv, cudaFuncAttributeMaxDynamicSharedMemorySize, GEMM_SMEM);
    cudaFuncSetAttribute(gemm_out, cudaFuncAttributeMaxDynamicSharedMemorySize, GEMM_SMEM);
    dim3 gq(DMODEL / 128, MROWS / 128, 3);
    gemm_qkv<<<gq, 256, GEMM_SMEM>>>(xhi, xlo);

    cudaFuncSetAttribute(attn_mma, cudaFuncAttributeMaxDynamicSharedMemorySize, ATTN_SMEM);
    attn_mma<<<dim3(SEQ / 128, BATCH * HEADS), 256, ATTN_SMEM>>>();

    dim3 gg(DMODEL / 128, MROWS / 128);
    gemm_out<<<gg, 256, GEMM_SMEM>>>(ahi, alo, (float*)d_out, bo);
}

// round 9
// speedup vs baseline: 1.8748x; 1.1390x over previous
#include <cuda_runtime.h>
#include <cuda_bf16.h>
#include <cuda_fp16.h>
#include <cstdint>

#define DMODEL 1024
#define BATCH  4
#define SEQ    2048
#define HEADS  16
#define HDIM   64
#define MROWS  (BATCH*SEQ)   // 8192

// ---------------- device scratch (allocation-free rule) ----------------
__device__ __half g_qhf[(size_t)MROWS * DMODEL];  // [B,H,T,hd] Q hi, pre-scaled 0.125
__device__ __half g_qlf[(size_t)MROWS * DMODEL];  // Q lo residual
__device__ __half g_k16[(size_t)MROWS * DMODEL];  // K single fp16
__device__ __half g_v16[(size_t)MROWS * DMODEL];  // V single fp16
__device__ __half g_xh16[(size_t)MROWS * DMODEL]; // x fp16 hi
__device__ __half g_xl16[(size_t)MROWS * DMODEL]; // x fp16 lo
__device__ __half g_w16[3][(size_t)DMODEL * DMODEL];     // Wq,Wk,Wv fp16
__device__ __nv_bfloat16 g_ahi[(size_t)MROWS * DMODEL];  // attn out [B,T,H*hd]
__device__ __nv_bfloat16 g_alo[(size_t)MROWS * DMODEL];
__device__ __nv_bfloat16 g_wohi[(size_t)DMODEL * DMODEL];// Wo bf16 hi/lo
__device__ __nv_bfloat16 g_wolo[(size_t)DMODEL * DMODEL];

// ---------------- portable PTX helpers (compute_80+) ----------------
__device__ __forceinline__ uint32_t smem_u32(const void* p) {
    uint32_t a;
    asm("{ .reg .u64 t; cvta.to.shared.u64 t, %1; cvt.u32.u64 %0, t; }"
        : "=r"(a) : "l"(p));
    return a;
}
#define CP_ASYNC16(dst, src) \
    asm volatile("cp.async.cg.shared.global [%0], [%1], 16;" \
                 :: "r"(dst), "l"(src) : "memory")
#define CP_COMMIT() asm volatile("cp.async.commit_group;" ::: "memory")
#define CP_WAIT0()  asm volatile("cp.async.wait_group 0;" ::: "memory")
#define CP_WAIT1()  asm volatile("cp.async.wait_group 1;" ::: "memory")

__device__ __forceinline__ void ldmx4(uint32_t* r, uint32_t addr) {
    asm volatile("ldmatrix.sync.aligned.m8n8.x4.shared.b16 {%0,%1,%2,%3}, [%4];"
                 : "=r"(r[0]), "=r"(r[1]), "=r"(r[2]), "=r"(r[3]) : "r"(addr));
}
__device__ __forceinline__ void ldmx2(uint32_t* r, uint32_t addr) {
    asm volatile("ldmatrix.sync.aligned.m8n8.x2.shared.b16 {%0,%1}, [%2];"
                 : "=r"(r[0]), "=r"(r[1]) : "r"(addr));
}
__device__ __forceinline__ void ldmx4t(uint32_t* r, uint32_t addr) {
    asm volatile("ldmatrix.sync.aligned.m8n8.x4.trans.shared.b16 {%0,%1,%2,%3}, [%4];"
                 : "=r"(r[0]), "=r"(r[1]), "=r"(r[2]), "=r"(r[3]) : "r"(addr));
}
__device__ __forceinline__ void mma_bf16(float* c, const uint32_t* a, const uint32_t* b) {
    asm volatile(
        "mma.sync.aligned.m16n8k16.row.col.f32.bf16.bf16.f32 "
        "{%0,%1,%2,%3}, {%4,%5,%6,%7}, {%8,%9}, {%0,%1,%2,%3};"
        : "+f"(c[0]), "+f"(c[1]), "+f"(c[2]), "+f"(c[3])
        : "r"(a[0]), "r"(a[1]), "r"(a[2]), "r"(a[3]), "r"(b[0]), "r"(b[1]));
}
__device__ __forceinline__ void mma_f16(float* c, const uint32_t* a, const uint32_t* b) {
    asm volatile(
        "mma.sync.aligned.m16n8k16.row.col.f32.f16.f16.f32 "
        "{%0,%1,%2,%3}, {%4,%5,%6,%7}, {%8,%9}, {%0,%1,%2,%3};"
        : "+f"(c[0]), "+f"(c[1]), "+f"(c[2]), "+f"(c[3])
        : "r"(a[0]), "r"(a[1]), "r"(a[2]), "r"(a[3]), "r"(b[0]), "r"(b[1]));
}
__device__ __forceinline__ uint32_t pk_bf16(float lo, float hi) {
    uint32_t d;
    asm("cvt.rn.bf16x2.f32 %0, %1, %2;" : "=r"(d) : "f"(hi), "f"(lo));
    return d;
}
__device__ __forceinline__ uint32_t pk_f16(float lo, float hi) {
    __half2 h = __floats2half2_rn(lo, hi);
    return *(uint32_t*)&h;
}
__device__ __forceinline__ float bf16_rnd(float v, float& res) {
    __nv_bfloat16 h = __float2bfloat16(v);
    float hf = __bfloat162float(h);
    res = v - hf;
    return hf;
}
__device__ __forceinline__ float f16_rnd(float v, float& res) {
    float hf = __half2float(__float2half_rn(v));
    res = v - hf;
    return hf;
}
// FFMA-only 2^y (clamped at -126); rel err ~1e-6
__device__ __forceinline__ float exp2p(float y) {
    y = fmaxf(y, -126.0f);
    float fl = floorf(y);
    float f  = y - fl;
    float p  = 1.5252734e-05f;
    p = fmaf(p, f, 1.5403530e-04f);
    p = fmaf(p, f, 1.3333558e-03f);
    p = fmaf(p, f, 9.6181291e-03f);
    p = fmaf(p, f, 5.5504109e-02f);
    p = fmaf(p, f, 2.4022651e-01f);
    p = fmaf(p, f, 6.9314718e-01f);
    p = fmaf(p, f, 1.0f);
    return p * __int_as_float(((int)fl + 127) << 23);
}
#define LOG2E 1.4426950408889634f

// ---------------- conversions ----------------
__global__ __launch_bounds__(256) void cvt_x16(
    const float4* __restrict__ in, uint2* __restrict__ hi,
    uint2* __restrict__ lo, int n4)
{
    int i = blockIdx.x * 256 + threadIdx.x;
    if (i >= n4) return;
    float4 v = in[i];
    float f[4] = {v.x, v.y, v.z, v.w};
    __half h[4], l[4];
    #pragma unroll
    for (int j = 0; j < 4; ++j) {
        float r;
        h[j] = __float2half_rn(f16_rnd(f[j], r));
        l[j] = __float2half_rn(r);
    }
    hi[i] = *(uint2*)h;
    lo[i] = *(uint2*)l;
}
// Wq/Wk/Wv -> single fp16 (blockIdx.y selects)
__global__ __launch_bounds__(256) void cvt_w3(
    const float4* __restrict__ w0, const float4* __restrict__ w1,
    const float4* __restrict__ w2, int n4)
{
    int i = blockIdx.x * 256 + threadIdx.x;
    if (i >= n4) return;
    const int y = blockIdx.y;
    const float4* src = (y == 0) ? w0 : (y == 1) ? w1 : w2;
    float4 v = src[i];
    __half h[4] = {__float2half_rn(v.x), __float2half_rn(v.y),
                   __float2half_rn(v.z), __float2half_rn(v.w)};
    ((uint2*)(&g_w16[0][0] + (size_t)y * DMODEL * DMODEL))[i] = *(uint2*)h;
}
// Wo -> bf16 hi/lo
__global__ __launch_bounds__(256) void cvt_wo(const float4* __restrict__ in, int n4)
{
    int i = blockIdx.x * 256 + threadIdx.x;
    if (i >= n4) return;
    float4 v = in[i];
    float f[4] = {v.x, v.y, v.z, v.w};
    __nv_bfloat16 h[4], l[4];
    #pragma unroll
    for (int j = 0; j < 4; ++j) {
        h[j] = __float2bfloat16(f[j]);
        l[j] = __float2bfloat16(f[j] - __bfloat162float(h[j]));
    }
    ((uint2*)g_wohi)[i] = *(uint2*)h;
    ((uint2*)g_wolo)[i] = *(uint2*)l;
}

#define PITCH   40                     // 16-bit elems per smem row (80 B)
#define TILE_B  (128 * PITCH * 2)      // 10240 B

// ---------------------------------------------------------------------------
// fp16 2-pass GEMM (QKV): C = (Ah+Al)[M,K] * B16[N,K]^T
// mode 1: fp16 hi/lo scatter (Q, scaled); mode 3: single fp16 scatter (K,V)
// ---------------------------------------------------------------------------
#define STAGE3_B   (3 * TILE_B)        // Ah, Al, B
#define GEMM16_SMEM (2 * STAGE3_B)     // 61440

__global__ __launch_bounds__(256, 1) void gemm_qkv(
    const __half* __restrict__ Ah, const __half* __restrict__ Al)
{
    extern __shared__ char smem[];
    const uint32_t sb = smem_u32(smem);
    const int tid  = threadIdx.x;
    const int wid  = tid >> 5, lane = tid & 31;
    const int wm   = wid & 1, wn = wid >> 1;
    const int m0   = blockIdx.y << 7;
    const int n0   = blockIdx.x << 7;
    const int z    = blockIdx.z;

    const __half* Bw = &g_w16[0][0] + (size_t)z * DMODEL * DMODEL;
    __half* H1 = (z == 0) ? g_qhf : (z == 1) ? g_k16 : g_v16;
    __half* H2 = g_qlf;
    const float scale = (z == 0) ? 0.125f : 1.0f;
    const int mode = (z == 0) ? 1 : 3;

    const __half* srcs[3] = {Ah, Al, Bw};

    auto prefetch = [&](int c, int st) {
        const int kk = c << 5;
        #pragma unroll
        for (int i = 0; i < 6; ++i) {
            int idx  = tid + i * 256;            // 0..1535
            int tile = idx >> 9;                 // 0..2
            int loc  = idx & 511;
            int r    = loc >> 2;
            int seg  = loc & 3;
            int rowb = (tile < 2) ? m0 : n0;
            const __half* src = srcs[tile] + (size_t)(rowb + r) * DMODEL + kk + seg * 8;
            uint32_t dst = sb + st * STAGE3_B + tile * TILE_B + r * (PITCH*2) + seg * 16;
            CP_ASYNC16(dst, src);
        }
        CP_COMMIT();
    };

    float acc[4][4][4] = {};
    prefetch(0, 0);

    for (int c = 0; c < 32; ++c) {
        const int st = c & 1;
        CP_WAIT0();
        __syncthreads();
        if (c + 1 < 32) prefetch(c + 1, st ^ 1);

        const uint32_t sA = sb + st * STAGE3_B;
        const uint32_t sB = sA + 2 * TILE_B;

        #pragma unroll
        for (int ks = 0; ks < 2; ++ks) {
            uint32_t ah[4][4], al[4][4], bb[4][2];
            const uint32_t kb = ks * 32;
            #pragma unroll
            for (int mi = 0; mi < 4; ++mi) {
                uint32_t off = (uint32_t)(wm*64 + mi*16 + (lane & 15)) * (PITCH*2)
                             + kb + (lane >> 4) * 16;
                ldmx4(ah[mi], sA + off);
                ldmx4(al[mi], sA + TILE_B + off);
            }
            #pragma unroll
            for (int ni = 0; ni < 4; ++ni) {
                int l16 = lane & 15;
                uint32_t off = (uint32_t)(wn*32 + ni*8 + (l16 & 7)) * (PITCH*2)
                             + kb + (l16 >> 3) * 16;
                ldmx2(bb[ni], sB + off);
            }
            #pragma unroll
            for (int mi = 0; mi < 4; ++mi)
                #pragma unroll
                for (int ni = 0; ni < 4; ++ni) {
                    mma_f16(acc[mi][ni], ah[mi], bb[ni]);
                    mma_f16(acc[mi][ni], al[mi], bb[ni]);
                }
        }
        __syncthreads();
    }

    const int r0 = wm * 64 + (lane >> 2);
    const int cbase = wn * 32 + (lane & 3) * 2;
    #pragma unroll
    for (int mi = 0; mi < 4; ++mi) {
        #pragma unroll
        for (int ni = 0; ni < 4; ++ni) {
            int n = n0 + cbase + ni * 8;
            #pragma unroll
            for (int half = 0; half < 2; ++half) {
                int m = m0 + r0 + mi * 16 + half * 8;
                float v0 = acc[mi][ni][half*2+0] * scale;
                float v1 = acc[mi][ni][half*2+1] * scale;
                int bbi = m >> 11, t = m & (SEQ - 1);
                int h = n >> 6, hd = n & 63;
                size_t off = (((size_t)bbi*HEADS + h)*SEQ + t)*HDIM + hd;
                if (mode == 1) {
                    float r0f, r1f;
                    float h0 = f16_rnd(v0, r0f);
                    float h1 = f16_rnd(v1, r1f);
                    *(uint32_t*)(H1 + off) = pk_f16(h0, h1);
                    *(uint32_t*)(H2 + off) = pk_f16(r0f, r1f);
                } else {
                    *(uint32_t*)(H1 + off) = pk_f16(v0, v1);
                }
            }
        }
    }
}

// ---------------------------------------------------------------------------
// bf16x3 output projection: C = (Ah+Al) * (Bh+Bl)^T + bias  (fp32 out)
// ---------------------------------------------------------------------------
#define STAGE4_B  (4 * TILE_B)
#define GEMMO_SMEM (2 * STAGE4_B)      // 81920

__global__ __launch_bounds__(256, 1) void gemm_out(
    const __nv_bfloat16* __restrict__ Ah, const __nv_bfloat16* __restrict__ Al,
    float* __restrict__ Cf, const float* __restrict__ bias)
{
    extern __shared__ char smem[];
    const uint32_t sb = smem_u32(smem);
    const int tid  = threadIdx.x;
    const int wid  = tid >> 5, lane = tid & 31;
    const int wm   = wid & 1, wn = wid >> 1;
    const int m0   = blockIdx.y << 7;
    const int n0   = blockIdx.x << 7;

    const __nv_bfloat16* srcs[4] = {Ah, Al, g_wohi, g_wolo};

    auto prefetch = [&](int c, int st) {
        const int kk = c << 5;
        #pragma unroll
        for (int i = 0; i < 8; ++i) {
            int idx  = tid + i * 256;
            int tile = idx >> 9;
            int loc  = idx & 511;
            int r    = loc >> 2;
            int seg  = loc & 3;
            int rowb = (tile < 2) ? m0 : n0;
            const __nv_bfloat16* src =
                srcs[tile] + (size_t)(rowb + r) * DMODEL + kk + seg * 8;
            uint32_t dst = sb + st * STAGE4_B + tile * TILE_B + r * (PITCH*2) + seg * 16;
            CP_ASYNC16(dst, src);
        }
        CP_COMMIT();
    };

    float acc[4][4][4] = {};
    prefetch(0, 0);

    for (int c = 0; c < 32; ++c) {
        const int st = c & 1;
        CP_WAIT0();
        __syncthreads();
        if (c + 1 < 32) prefetch(c + 1, st ^ 1);

        const uint32_t sA = sb + st * STAGE4_B;
        const uint32_t sB = sA + 2 * TILE_B;

        #pragma unroll
        for (int ks = 0; ks < 2; ++ks) {
            uint32_t ah[4][4], al[4][4], bh[4][2], bl[4][2];
            const uint32_t kb = ks * 32;
            #pragma unroll
            for (int mi = 0; mi < 4; ++mi) {
                uint32_t off = (uint32_t)(wm*64 + mi*16 + (lane & 15)) * (PITCH*2)
                             + kb + (lane >> 4) * 16;
                ldmx4(ah[mi], sA + off);
                ldmx4(al[mi], sA + TILE_B + off);
            }
            #pragma unroll
            for (int ni = 0; ni < 4; ++ni) {
                int l16 = lane & 15;
                uint32_t off = (uint32_t)(wn*32 + ni*8 + (l16 & 7)) * (PITCH*2)
                             + kb + (l16 >> 3) * 16;
                ldmx2(bh[ni], sB + off);
                ldmx2(bl[ni], sB + TILE_B + off);
            }
            #pragma unroll
            for (int mi = 0; mi < 4; ++mi)
                #pragma unroll
                for (int ni = 0; ni < 4; ++ni) {
                    mma_bf16(acc[mi][ni], ah[mi], bh[ni]);
                    mma_bf16(acc[mi][ni], ah[mi], bl[ni]);
                    mma_bf16(acc[mi][ni], al[mi], bh[ni]);
                }
        }
        __syncthreads();
    }

    const int r0 = wm * 64 + (lane >> 2);
    const int cbase = wn * 32 + (lane & 3) * 2;
    #pragma unroll
    for (int mi = 0; mi < 4; ++mi) {
        #pragma unroll
        for (int ni = 0; ni < 4; ++ni) {
            int n = n0 + cbase + ni * 8;
            float2 bv = *(const float2*)(bias + n);
            #pragma unroll
            for (int half = 0; half < 2; ++half) {
                int m = m0 + r0 + mi * 16 + half * 8;
                *(float2*)(Cf + (size_t)m*DMODEL + n) =
                    make_float2(acc[mi][ni][half*2+0] + bv.x,
                                acc[mi][ni][half*2+1] + bv.y);
            }
        }
    }
}

// ---------------------------------------------------------------------------
// fp16 tensor-core flash attention, shift-free softmax.
// QK^T: (qh+ql) * k16 (2 passes); PV: p16 * v16 (1 pass)
// ---------------------------------------------------------------------------
#define APB       144
#define AQ_BYTES  (128 * APB)
#define AKV_BYTES (64 * APB)
#define ASTAGE    (2 * AKV_BYTES)
#define ATTN_SMEM (2 * AQ_BYTES + 2 * ASTAGE)  // 73728

__global__ __launch_bounds__(256, 1) void attn_mma()
{
    extern __shared__ char sm[];
    const uint32_t sb = smem_u32(sm);
    const int tid = threadIdx.x;
    const int wid = tid >> 5, lane = tid & 31;
    const int bh  = blockIdx.y;
    const int q0  = blockIdx.x << 7;

    const uint32_t sQh = sb, sQl = sb + AQ_BYTES;
    const uint32_t sKV = sb + 2 * AQ_BYTES;

    const size_t qbase = ((size_t)bh * SEQ + q0) * HDIM;
    #pragma unroll
    for (int i = 0; i < 8; ++i) {
        int idx = tid + i * 256;
        int arr = idx >> 10, loc = idx & 1023, row = loc >> 3, seg = loc & 7;
        const __half* src = (arr ? g_qlf : g_qhf) + qbase + (size_t)row * HDIM + seg * 8;
        uint32_t dst = (arr ? sQl : sQh) + row * APB + seg * 16;
        CP_ASYNC16(dst, src);
    }
    auto prefetch_kv = [&](int kt, int st) {
        const size_t kb = ((size_t)bh * SEQ + kt * 64) * HDIM;
        #pragma unroll
        for (int i = 0; i < 4; ++i) {
            int idx = tid + i * 256;
            int arr = idx >> 9, loc = idx & 511, row = loc >> 3, seg = loc & 7;
            const __half* src = (arr ? g_v16 : g_k16) + kb + (size_t)row * HDIM + seg * 8;
            uint32_t dst = sKV + st * ASTAGE + arr * AKV_BYTES + row * APB + seg * 16;
            CP_ASYNC16(dst, src);
        }
    };
    prefetch_kv(0, 0); CP_COMMIT();
    prefetch_kv(1, 1); CP_COMMIT();

    CP_WAIT1();
    __syncthreads();
    uint32_t qh[4][4], ql[4][4];
    #pragma unroll
    for (int ks = 0; ks < 4; ++ks) {
        uint32_t off = (uint32_t)(wid*16 + (lane & 15)) * APB + (lane >> 4) * 16 + ks * 32;
        ldmx4(qh[ks], sQh + off);
        ldmx4(ql[ks], sQl + off);
    }

    float o[8][4] = {};
    float li[2] = {};

    for (int kt = 0; kt < SEQ / 64; ++kt) {
        const int st = kt & 1;
        CP_WAIT1();
        __syncthreads();
        const uint32_t sK = sKV + st * ASTAGE;
        const uint32_t sV = sK + AKV_BYTES;

        float s[8][4] = {};
        #pragma unroll
        for (int ks = 0; ks < 4; ++ks) {
            #pragma unroll
            for (int np = 0; np < 4; ++np) {
                uint32_t k4[4];
                uint32_t key  = np*16 + ((lane >> 4) << 3) + (lane & 7);
                uint32_t koff = ks*32 + ((lane >> 3) & 1) * 16;
                uint32_t a = key * APB + koff;
                ldmx4(k4, sK + a);
                mma_f16(s[2*np],   qh[ks], k4);
                mma_f16(s[2*np],   ql[ks], k4);
                mma_f16(s[2*np+1], qh[ks], k4 + 2);
                mma_f16(s[2*np+1], ql[ks], k4 + 2);
            }
        }

        {
            float l0 = 0.f, l1 = 0.f;
            #pragma unroll
            for (int nt = 0; nt < 8; ++nt) {
                float e0 = exp2p(s[nt][0] * LOG2E);
                float e1 = exp2p(s[nt][1] * LOG2E);
                float e2 = exp2p(s[nt][2] * LOG2E);
                float e3 = exp2p(s[nt][3] * LOG2E);
                s[nt][0] = e0; s[nt][1] = e1;
                s[nt][2] = e2; s[nt][3] = e3;
                l0 += e0 + e1;
                l1 += e2 + e3;
            }
            li[0] += l0; li[1] += l1;
        }

        #pragma unroll
        for (int ks = 0; ks < 4; ++ks) {
            uint32_t pa[4];
            #pragma unroll
            for (int half = 0; half < 2; ++half) {
                const float* sv = s[2*ks + half];
                pa[2*half]   = pk_f16(sv[0], sv[1]);
                pa[2*half+1] = pk_f16(sv[2], sv[3]);
            }
            #pragma unroll
            for (int njp = 0; njp < 4; ++njp) {
                uint32_t v4[4];
                uint32_t key  = ks*16 + ((lane >> 3) & 1) * 8 + (lane & 7);
                uint32_t colb = (2*njp + (lane >> 4)) * 16;
                uint32_t a = key * APB + colb;
                ldmx4t(v4, sV + a);
                mma_f16(o[2*njp],   pa, v4);
                mma_f16(o[2*njp+1], pa, v4 + 2);
            }
        }

        __syncthreads();
        if (kt + 2 < SEQ / 64) prefetch_kv(kt + 2, st);
        CP_COMMIT();
    }

    #pragma unroll
    for (int rr = 0; rr < 2; ++rr) {
        li[rr] += __shfl_xor_sync(0xffffffffu, li[rr], 1);
        li[rr] += __shfl_xor_sync(0xffffffffu, li[rr], 2);
    }
    const int b = bh >> 4, h = bh & 15;
    #pragma unroll
    for (int rr = 0; rr < 2; ++rr) {
        float inv = 1.0f / (li[rr] + 1e-8f);
        int t = q0 + wid*16 + (lane >> 2) + rr*8;
        size_t base = ((size_t)b * SEQ + t) * DMODEL + h * HDIM;
        #pragma unroll
        for (int nt = 0; nt < 8; ++nt) {
            int col = nt*8 + (lane & 3)*2;
            float v0 = o[nt][2*rr]   * inv;
            float v1 = o[nt][2*rr+1] * inv;
            float r0f, r1f;
            float h0 = bf16_rnd(v0, r0f);
            float h1 = bf16_rnd(v1, r1f);
            *(uint32_t*)(g_ahi + base + col) = pk_bf16(h0, h1);
            *(uint32_t*)(g_alo + base + col) = pk_bf16(r0f, r1f);
        }
    }
}

// ---------------------------------------------------------------------------
extern "C" void kernel_launch(void* const* d_in, const int* in_sizes, int n_in,
                              void* d_out, int out_size)
{
    const float* x  = (const float*)d_in[0];
    const float* Wq = (const float*)d_in[1];
    const float* Wk = (const float*)d_in[2];
    const float* Wv = (const float*)d_in[3];
    const float* Wo = (const float*)d_in[4];
    const float* bo = (const float*)d_in[5];

    __half *xh16, *xl16;
    __nv_bfloat16 *ahi, *alo;
    cudaGetSymbolAddress((void**)&xh16, g_xh16);
    cudaGetSymbolAddress((void**)&xl16, g_xl16);
    cudaGetSymbolAddress((void**)&ahi, g_ahi);
    cudaGetSymbolAddress((void**)&alo, g_alo);

    const int NX4 = MROWS * DMODEL / 4;
    const int NW4 = DMODEL * DMODEL / 4;

    cvt_x16<<<(NX4 + 255) / 256, 256>>>((const float4*)x, (uint2*)xh16, (uint2*)xl16, NX4);
    cvt_w3<<<dim3((NW4 + 255) / 256, 3), 256>>>(
        (const float4*)Wq, (const float4*)Wk, (const float4*)Wv, NW4);
    cvt_wo<<<(NW4 + 255) / 256, 256>>>((const float4*)Wo, NW4);

    cudaFuncSetAttribute(gemm_qkv, cudaFuncAttributeMaxDynamicSharedMemorySize, GEMM16_SMEM);
    cudaFuncSetAttribute(gemm_out, cudaFuncAttributeMaxDynamicSharedMemorySize, GEMMO_SMEM);
    dim3 gq(DMODEL / 128, MROWS / 128, 3);
    gemm_qkv<<<gq, 256, GEMM16_SMEM>>>(xh16, xl16);

    cudaFuncSetAttribute(attn_mma, cudaFuncAttributeMaxDynamicSharedMemorySize, ATTN_SMEM);
    attn_mma<<<dim3(SEQ / 128, BATCH * HEADS), 256, ATTN_SMEM>>>();

    dim3 gg(DMODEL / 128, MROWS / 128);
    gemm_out<<<gg, 256, GEMMO_SMEM>>>(ahi, alo, (float*)d_out, bo);
}

// round 14
// speedup vs baseline: 2.0532x; 1.0952x over previous
#include <cuda_runtime.h>
#include <cuda_bf16.h>
#include <cuda_fp16.h>
#include <cstdint>

#define DMODEL 1024
#define BATCH  4
#define SEQ    2048
#define HEADS  16
#define HDIM   64
#define MROWS  (BATCH*SEQ)   // 8192

// ---------------- device scratch (allocation-free rule) ----------------
__device__ __half g_qhf[(size_t)MROWS * DMODEL];  // [B,H,T,hd] Q hi, pre-scaled 0.125
__device__ __half g_qlf[(size_t)MROWS * DMODEL];  // Q lo residual
__device__ __half g_k16[(size_t)MROWS * DMODEL];  // K single fp16
__device__ __half g_v16[(size_t)MROWS * DMODEL];  // V single fp16
__device__ __half g_xh16[(size_t)MROWS * DMODEL]; // x fp16 hi
__device__ __half g_xl16[(size_t)MROWS * DMODEL]; // x fp16 lo
__device__ __half g_w16[3][(size_t)DMODEL * DMODEL];     // Wq,Wk,Wv fp16
__device__ __nv_bfloat16 g_ahi[(size_t)MROWS * DMODEL];  // attn out [B,T,H*hd]
__device__ __nv_bfloat16 g_alo[(size_t)MROWS * DMODEL];
__device__ __nv_bfloat16 g_wohi[(size_t)DMODEL * DMODEL];// Wo bf16 hi/lo
__device__ __nv_bfloat16 g_wolo[(size_t)DMODEL * DMODEL];

// ---------------- portable PTX helpers (compute_80+) ----------------
__device__ __forceinline__ uint32_t smem_u32(const void* p) {
    uint32_t a;
    asm("{ .reg .u64 t; cvta.to.shared.u64 t, %1; cvt.u32.u64 %0, t; }"
        : "=r"(a) : "l"(p));
    return a;
}
#define CP_ASYNC16(dst, src) \
    asm volatile("cp.async.cg.shared.global [%0], [%1], 16;" \
                 :: "r"(dst), "l"(src) : "memory")
#define CP_COMMIT() asm volatile("cp.async.commit_group;" ::: "memory")
#define CP_WAIT0()  asm volatile("cp.async.wait_group 0;" ::: "memory")
#define CP_WAIT1()  asm volatile("cp.async.wait_group 1;" ::: "memory")

__device__ __forceinline__ void ldmx4(uint32_t* r, uint32_t addr) {
    asm volatile("ldmatrix.sync.aligned.m8n8.x4.shared.b16 {%0,%1,%2,%3}, [%4];"
                 : "=r"(r[0]), "=r"(r[1]), "=r"(r[2]), "=r"(r[3]) : "r"(addr));
}
__device__ __forceinline__ void ldmx2(uint32_t* r, uint32_t addr) {
    asm volatile("ldmatrix.sync.aligned.m8n8.x2.shared.b16 {%0,%1}, [%2];"
                 : "=r"(r[0]), "=r"(r[1]) : "r"(addr));
}
__device__ __forceinline__ void ldmx4t(uint32_t* r, uint32_t addr) {
    asm volatile("ldmatrix.sync.aligned.m8n8.x4.trans.shared.b16 {%0,%1,%2,%3}, [%4];"
                 : "=r"(r[0]), "=r"(r[1]), "=r"(r[2]), "=r"(r[3]) : "r"(addr));
}
__device__ __forceinline__ void mma_bf16(float* c, const uint32_t* a, const uint32_t* b) {
    asm volatile(
        "mma.sync.aligned.m16n8k16.row.col.f32.bf16.bf16.f32 "
        "{%0,%1,%2,%3}, {%4,%5,%6,%7}, {%8,%9}, {%0,%1,%2,%3};"
        : "+f"(c[0]), "+f"(c[1]), "+f"(c[2]), "+f"(c[3])
        : "r"(a[0]), "r"(a[1]), "r"(a[2]), "r"(a[3]), "r"(b[0]), "r"(b[1]));
}
__device__ __forceinline__ void mma_f16(float* c, const uint32_t* a, const uint32_t* b) {
    asm volatile(
        "mma.sync.aligned.m16n8k16.row.col.f32.f16.f16.f32 "
        "{%0,%1,%2,%3}, {%4,%5,%6,%7}, {%8,%9}, {%0,%1,%2,%3};"
        : "+f"(c[0]), "+f"(c[1]), "+f"(c[2]), "+f"(c[3])
        : "r"(a[0]), "r"(a[1]), "r"(a[2]), "r"(a[3]), "r"(b[0]), "r"(b[1]));
}
__device__ __forceinline__ uint32_t pk_bf16(float lo, float hi) {
    uint32_t d;
    asm("cvt.rn.bf16x2.f32 %0, %1, %2;" : "=r"(d) : "f"(hi), "f"(lo));
    return d;
}
__device__ __forceinline__ uint32_t pk_f16(float lo, float hi) {
    __half2 h = __floats2half2_rn(lo, hi);
    return *(uint32_t*)&h;
}
__device__ __forceinline__ float bf16_rnd(float v, float& res) {
    __nv_bfloat16 h = __float2bfloat16(v);
    float hf = __bfloat162float(h);
    res = v - hf;
    return hf;
}
__device__ __forceinline__ float f16_rnd(float v, float& res) {
    float hf = __half2float(__float2half_rn(v));
    res = v - hf;
    return hf;
}
// FFMA-only 2^y (clamped at -126); rel err ~1e-6
__device__ __forceinline__ float exp2p(float y) {
    y = fmaxf(y, -126.0f);
    float fl = floorf(y);
    float f  = y - fl;
    float p  = 1.5252734e-05f;
    p = fmaf(p, f, 1.5403530e-04f);
    p = fmaf(p, f, 1.3333558e-03f);
    p = fmaf(p, f, 9.6181291e-03f);
    p = fmaf(p, f, 5.5504109e-02f);
    p = fmaf(p, f, 2.4022651e-01f);
    p = fmaf(p, f, 6.9314718e-01f);
    p = fmaf(p, f, 1.0f);
    return p * __int_as_float(((int)fl + 127) << 23);
}
#define LOG2E 1.4426950408889634f

// ---------------- conversions ----------------
__global__ __launch_bounds__(256) void cvt_x16(
    const float4* __restrict__ in, uint2* __restrict__ hi,
    uint2* __restrict__ lo, int n4)
{
    int i = blockIdx.x * 256 + threadIdx.x;
    if (i >= n4) return;
    float4 v = in[i];
    float f[4] = {v.x, v.y, v.z, v.w};
    __half h[4], l[4];
    #pragma unroll
    for (int j = 0; j < 4; ++j) {
        float r;
        h[j] = __float2half_rn(f16_rnd(f[j], r));
        l[j] = __float2half_rn(r);
    }
    hi[i] = *(uint2*)h;
    lo[i] = *(uint2*)l;
}
__global__ __launch_bounds__(256) void cvt_w3(
    const float4* __restrict__ w0, const float4* __restrict__ w1,
    const float4* __restrict__ w2, int n4)
{
    int i = blockIdx.x * 256 + threadIdx.x;
    if (i >= n4) return;
    const int y = blockIdx.y;
    const float4* src = (y == 0) ? w0 : (y == 1) ? w1 : w2;
    float4 v = src[i];
    __half h[4] = {__float2half_rn(v.x), __float2half_rn(v.y),
                   __float2half_rn(v.z), __float2half_rn(v.w)};
    ((uint2*)(&g_w16[0][0] + (size_t)y * DMODEL * DMODEL))[i] = *(uint2*)h;
}
__global__ __launch_bounds__(256) void cvt_wo(const float4* __restrict__ in, int n4)
{
    int i = blockIdx.x * 256 + threadIdx.x;
    if (i >= n4) return;
    float4 v = in[i];
    float f[4] = {v.x, v.y, v.z, v.w};
    __nv_bfloat16 h[4], l[4];
    #pragma unroll
    for (int j = 0; j < 4; ++j) {
        h[j] = __float2bfloat16(f[j]);
        l[j] = __float2bfloat16(f[j] - __bfloat162float(h[j]));
    }
    ((uint2*)g_wohi)[i] = *(uint2*)h;
    ((uint2*)g_wolo)[i] = *(uint2*)l;
}

#define PITCH   40                     // 16-bit elems per smem row (80 B)
#define TILE_B  (128 * PITCH * 2)      // 10240 B

// ---------------------------------------------------------------------------
// fp16 2-pass GEMM (QKV): C = (Ah+Al)[M,K] * B16[N,K]^T   — 2 CTAs/SM
// ---------------------------------------------------------------------------
#define STAGE3_B   (3 * TILE_B)        // Ah, Al, B
#define GEMM16_SMEM (2 * STAGE3_B)     // 61440

__global__ __launch_bounds__(256, 2) void gemm_qkv(
    const __half* __restrict__ Ah, const __half* __restrict__ Al)
{
    extern __shared__ char smem[];
    const uint32_t sb = smem_u32(smem);
    const int tid  = threadIdx.x;
    const int wid  = tid >> 5, lane = tid & 31;
    const int wm   = wid & 1, wn = wid >> 1;
    const int m0   = blockIdx.y << 7;
    const int n0   = blockIdx.x << 7;
    const int z    = blockIdx.z;

    const __half* Bw = &g_w16[0][0] + (size_t)z * DMODEL * DMODEL;
    __half* H1 = (z == 0) ? g_qhf : (z == 1) ? g_k16 : g_v16;
    __half* H2 = g_qlf;
    const float scale = (z == 0) ? 0.125f : 1.0f;
    const int mode = (z == 0) ? 1 : 3;

    const __half* srcs[3] = {Ah, Al, Bw};

    auto prefetch = [&](int c, int st) {
        const int kk = c << 5;
        #pragma unroll
        for (int i = 0; i < 6; ++i) {
            int idx  = tid + i * 256;            // 0..1535
            int tile = idx >> 9;                 // 0..2
            int loc  = idx & 511;
            int r    = loc >> 2;
            int seg  = loc & 3;
            int rowb = (tile < 2) ? m0 : n0;
            const __half* src = srcs[tile] + (size_t)(rowb + r) * DMODEL + kk + seg * 8;
            uint32_t dst = sb + st * STAGE3_B + tile * TILE_B + r * (PITCH*2) + seg * 16;
            CP_ASYNC16(dst, src);
        }
        CP_COMMIT();
    };

    float acc[4][4][4] = {};
    prefetch(0, 0);

    for (int c = 0; c < 32; ++c) {
        const int st = c & 1;
        CP_WAIT0();
        __syncthreads();
        if (c + 1 < 32) prefetch(c + 1, st ^ 1);

        const uint32_t sA = sb + st * STAGE3_B;
        const uint32_t sB = sA + 2 * TILE_B;

        #pragma unroll
        for (int ks = 0; ks < 2; ++ks) {
            uint32_t ah[4][4], al[4][4], bb[4][2];
            const uint32_t kb = ks * 32;
            #pragma unroll
            for (int mi = 0; mi < 4; ++mi) {
                uint32_t off = (uint32_t)(wm*64 + mi*16 + (lane & 15)) * (PITCH*2)
                             + kb + (lane >> 4) * 16;
                ldmx4(ah[mi], sA + off);
                ldmx4(al[mi], sA + TILE_B + off);
            }
            #pragma unroll
            for (int ni = 0; ni < 4; ++ni) {
                int l16 = lane & 15;
                uint32_t off = (uint32_t)(wn*32 + ni*8 + (l16 & 7)) * (PITCH*2)
                             + kb + (l16 >> 3) * 16;
                ldmx2(bb[ni], sB + off);
            }
            #pragma unroll
            for (int mi = 0; mi < 4; ++mi)
                #pragma unroll
                for (int ni = 0; ni < 4; ++ni) {
                    mma_f16(acc[mi][ni], ah[mi], bb[ni]);
                    mma_f16(acc[mi][ni], al[mi], bb[ni]);
                }
        }
        __syncthreads();
    }

    const int r0 = wm * 64 + (lane >> 2);
    const int cbase = wn * 32 + (lane & 3) * 2;
    #pragma unroll
    for (int mi = 0; mi < 4; ++mi) {
        #pragma unroll
        for (int ni = 0; ni < 4; ++ni) {
            int n = n0 + cbase + ni * 8;
            #pragma unroll
            for (int half = 0; half < 2; ++half) {
                int m = m0 + r0 + mi * 16 + half * 8;
                float v0 = acc[mi][ni][half*2+0] * scale;
                float v1 = acc[mi][ni][half*2+1] * scale;
                int bbi = m >> 11, t = m & (SEQ - 1);
                int h = n >> 6, hd = n & 63;
                size_t off = (((size_t)bbi*HEADS + h)*SEQ + t)*HDIM + hd;
                if (mode == 1) {
                    float r0f, r1f;
                    float h0 = f16_rnd(v0, r0f);
                    float h1 = f16_rnd(v1, r1f);
                    *(uint32_t*)(H1 + off) = pk_f16(h0, h1);
                    *(uint32_t*)(H2 + off) = pk_f16(r0f, r1f);
                } else {
                    *(uint32_t*)(H1 + off) = pk_f16(v0, v1);
                }
            }
        }
    }
}

// ---------------------------------------------------------------------------
// bf16x3 output projection: C = (Ah+Al) * (Bh+Bl)^T + bias  — 2 CTAs/SM
// ---------------------------------------------------------------------------
#define STAGE4_B  (4 * TILE_B)
#define GEMMO_SMEM (2 * STAGE4_B)      // 81920

__global__ __launch_bounds__(256, 2) void gemm_out(
    const __nv_bfloat16* __restrict__ Ah, const __nv_bfloat16* __restrict__ Al,
    float* __restrict__ Cf, const float* __restrict__ bias)
{
    extern __shared__ char smem[];
    const uint32_t sb = smem_u32(smem);
    const int tid  = threadIdx.x;
    const int wid  = tid >> 5, lane = tid & 31;
    const int wm   = wid & 1, wn = wid >> 1;
    const int m0   = blockIdx.y << 7;
    const int n0   = blockIdx.x << 7;

    const __nv_bfloat16* srcs[4] = {Ah, Al, g_wohi, g_wolo};

    auto prefetch = [&](int c, int st) {
        const int kk = c << 5;
        #pragma unroll
        for (int i = 0; i < 8; ++i) {
            int idx  = tid + i * 256;
            int tile = idx >> 9;
            int loc  = idx & 511;
            int r    = loc >> 2;
            int seg  = loc & 3;
            int rowb = (tile < 2) ? m0 : n0;
            const __nv_bfloat16* src =
                srcs[tile] + (size_t)(rowb + r) * DMODEL + kk + seg * 8;
            uint32_t dst = sb + st * STAGE4_B + tile * TILE_B + r * (PITCH*2) + seg * 16;
            CP_ASYNC16(dst, src);
        }
        CP_COMMIT();
    };

    float acc[4][4][4] = {};
    prefetch(0, 0);

    for (int c = 0; c < 32; ++c) {
        const int st = c & 1;
        CP_WAIT0();
        __syncthreads();
        if (c + 1 < 32) prefetch(c + 1, st ^ 1);

        const uint32_t sA = sb + st * STAGE4_B;
        const uint32_t sB = sA + 2 * TILE_B;

        #pragma unroll
        for (int ks = 0; ks < 2; ++ks) {
            uint32_t ah[4][4], al[4][4], bh[4][2], bl[4][2];
            const uint32_t kb = ks * 32;
            #pragma unroll
            for (int mi = 0; mi < 4; ++mi) {
                uint32_t off = (uint32_t)(wm*64 + mi*16 + (lane & 15)) * (PITCH*2)
                             + kb + (lane >> 4) * 16;
                ldmx4(ah[mi], sA + off);
                ldmx4(al[mi], sA + TILE_B + off);
            }
            #pragma unroll
            for (int ni = 0; ni < 4; ++ni) {
                int l16 = lane & 15;
                uint32_t off = (uint32_t)(wn*32 + ni*8 + (l16 & 7)) * (PITCH*2)
                             + kb + (l16 >> 3) * 16;
                ldmx2(bh[ni], sB + off);
                ldmx2(bl[ni], sB + TILE_B + off);
            }
            #pragma unroll
            for (int mi = 0; mi < 4; ++mi)
                #pragma unroll
                for (int ni = 0; ni < 4; ++ni) {
                    mma_bf16(acc[mi][ni], ah[mi], bh[ni]);
                    mma_bf16(acc[mi][ni], ah[mi], bl[ni]);
                    mma_bf16(acc[mi][ni], al[mi], bh[ni]);
                }
        }
        __syncthreads();
    }

    const int r0 = wm * 64 + (lane >> 2);
    const int cbase = wn * 32 + (lane & 3) * 2;
    #pragma unroll
    for (int mi = 0; mi < 4; ++mi) {
        #pragma unroll
        for (int ni = 0; ni < 4; ++ni) {
            int n = n0 + cbase + ni * 8;
            float2 bv = *(const float2*)(bias + n);
            #pragma unroll
            for (int half = 0; half < 2; ++half) {
                int m = m0 + r0 + mi * 16 + half * 8;
                *(float2*)(Cf + (size_t)m*DMODEL + n) =
                    make_float2(acc[mi][ni][half*2+0] + bv.x,
                                acc[mi][ni][half*2+1] + bv.y);
            }
        }
    }
}

// ---------------------------------------------------------------------------
// fp16 tensor-core flash attention (unchanged from R9)
// ---------------------------------------------------------------------------
#define APB       144
#define AQ_BYTES  (128 * APB)
#define AKV_BYTES (64 * APB)
#define ASTAGE    (2 * AKV_BYTES)
#define ATTN_SMEM (2 * AQ_BYTES + 2 * ASTAGE)  // 73728

__global__ __launch_bounds__(256, 1) void attn_mma()
{
    extern __shared__ char sm[];
    const uint32_t sb = smem_u32(sm);
    const int tid = threadIdx.x;
    const int wid = tid >> 5, lane = tid & 31;
    const int bh  = blockIdx.y;
    const int q0  = blockIdx.x << 7;

    const uint32_t sQh = sb, sQl = sb + AQ_BYTES;
    const uint32_t sKV = sb + 2 * AQ_BYTES;

    const size_t qbase = ((size_t)bh * SEQ + q0) * HDIM;
    #pragma unroll
    for (int i = 0; i < 8; ++i) {
        int idx = tid + i * 256;
        int arr = idx >> 10, loc = idx & 1023, row = loc >> 3, seg = loc & 7;
        const __half* src = (arr ? g_qlf : g_qhf) + qbase + (size_t)row * HDIM + seg * 8;
        uint32_t dst = (arr ? sQl : sQh) + row * APB + seg * 16;
        CP_ASYNC16(dst, src);
    }
    auto prefetch_kv = [&](int kt, int st) {
        const size_t kb = ((size_t)bh * SEQ + kt * 64) * HDIM;
        #pragma unroll
        for (int i = 0; i < 4; ++i) {
            int idx = tid + i * 256;
            int arr = idx >> 9, loc = idx & 511, row = loc >> 3, seg = loc & 7;
            const __half* src = (arr ? g_v16 : g_k16) + kb + (size_t)row * HDIM + seg * 8;
            uint32_t dst = sKV + st * ASTAGE + arr * AKV_BYTES + row * APB + seg * 16;
            CP_ASYNC16(dst, src);
        }
    };
    prefetch_kv(0, 0); CP_COMMIT();
    prefetch_kv(1, 1); CP_COMMIT();

    CP_WAIT1();
    __syncthreads();
    uint32_t qh[4][4], ql[4][4];
    #pragma unroll
    for (int ks = 0; ks < 4; ++ks) {
        uint32_t off = (uint32_t)(wid*16 + (lane & 15)) * APB + (lane >> 4) * 16 + ks * 32;
        ldmx4(qh[ks], sQh + off);
        ldmx4(ql[ks], sQl + off);
    }

    float o[8][4] = {};
    float li[2] = {};

    for (int kt = 0; kt < SEQ / 64; ++kt) {
        const int st = kt & 1;
        CP_WAIT1();
        __syncthreads();
        const uint32_t sK = sKV + st * ASTAGE;
        const uint32_t sV = sK + AKV_BYTES;

        float s[8][4] = {};
        #pragma unroll
        for (int ks = 0; ks < 4; ++ks) {
            #pragma unroll
            for (int np = 0; np < 4; ++np) {
                uint32_t k4[4];
                uint32_t key  = np*16 + ((lane >> 4) << 3) + (lane & 7);
                uint32_t koff = ks*32 + ((lane >> 3) & 1) * 16;
                uint32_t a = key * APB + koff;
                ldmx4(k4, sK + a);
                mma_f16(s[2*np],   qh[ks], k4);
                mma_f16(s[2*np],   ql[ks], k4);
                mma_f16(s[2*np+1], qh[ks], k4 + 2);
                mma_f16(s[2*np+1], ql[ks], k4 + 2);
            }
        }

        {
            float l0 = 0.f, l1 = 0.f;
            #pragma unroll
            for (int nt = 0; nt < 8; ++nt) {
                float e0 = exp2p(s[nt][0] * LOG2E);
                float e1 = exp2p(s[nt][1] * LOG2E);
                float e2 = exp2p(s[nt][2] * LOG2E);
                float e3 = exp2p(s[nt][3] * LOG2E);
                s[nt][0] = e0; s[nt][1] = e1;
                s[nt][2] = e2; s[nt][3] = e3;
                l0 += e0 + e1;
                l1 += e2 + e3;
            }
            li[0] += l0; li[1] += l1;
        }

        #pragma unroll
        for (int ks = 0; ks < 4; ++ks) {
            uint32_t pa[4];
            #pragma unroll
            for (int half = 0; half < 2; ++half) {
                const float* sv = s[2*ks + half];
                pa[2*half]   = pk_f16(sv[0], sv[1]);
                pa[2*half+1] = pk_f16(sv[2], sv[3]);
            }
            #pragma unroll
            for (int njp = 0; njp < 4; ++njp) {
                uint32_t v4[4];
                uint32_t key  = ks*16 + ((lane >> 3) & 1) * 8 + (lane & 7);
                uint32_t colb = (2*njp + (lane >> 4)) * 16;
                uint32_t a = key * APB + colb;
                ldmx4t(v4, sV + a);
                mma_f16(o[2*njp],   pa, v4);
                mma_f16(o[2*njp+1], pa, v4 + 2);
            }
        }

        __syncthreads();
        if (kt + 2 < SEQ / 64) prefetch_kv(kt + 2, st);
        CP_COMMIT();
    }

    #pragma unroll
    for (int rr = 0; rr < 2; ++rr) {
        li[rr] += __shfl_xor_sync(0xffffffffu, li[rr], 1);
        li[rr] += __shfl_xor_sync(0xffffffffu, li[rr], 2);
    }
    const int b = bh >> 4, h = bh & 15;
    #pragma unroll
    for (int rr = 0; rr < 2; ++rr) {
        float inv = 1.0f / (li[rr] + 1e-8f);
        int t = q0 + wid*16 + (lane >> 2) + rr*8;
        size_t base = ((size_t)b * SEQ + t) * DMODEL + h * HDIM;
        #pragma unroll
        for (int nt = 0; nt < 8; ++nt) {
            int col = nt*8 + (lane & 3)*2;
            float v0 = o[nt][2*rr]   * inv;
            float v1 = o[nt][2*rr+1] * inv;
            float r0f, r1f;
            float h0 = bf16_rnd(v0, r0f);
            float h1 = bf16_rnd(v1, r1f);
            *(uint32_t*)(g_ahi + base + col) = pk_bf16(h0, h1);
            *(uint32_t*)(g_alo + base + col) = pk_bf16(r0f, r1f);
        }
    }
}

// ---------------------------------------------------------------------------
extern "C" void kernel_launch(void* const* d_in, const int* in_sizes, int n_in,
                              void* d_out, int out_size)
{
    const float* x  = (const float*)d_in[0];
    const float* Wq = (const float*)d_in[1];
    const float* Wk = (const float*)d_in[2];
    const float* Wv = (const float*)d_in[3];
    const float* Wo = (const float*)d_in[4];
    const float* bo = (const float*)d_in[5];

    __half *xh16, *xl16;
    __nv_bfloat16 *ahi, *alo;
    cudaGetSymbolAddress((void**)&xh16, g_xh16);
    cudaGetSymbolAddress((void**)&xl16, g_xl16);
    cudaGetSymbolAddress((void**)&ahi, g_ahi);
    cudaGetSymbolAddress((void**)&alo, g_alo);

    const int NX4 = MROWS * DMODEL / 4;
    const int NW4 = DMODEL * DMODEL / 4;

    cvt_x16<<<(NX4 + 255) / 256, 256>>>((const float4*)x, (uint2*)xh16, (uint2*)xl16, NX4);
    cvt_w3<<<dim3((NW4 + 255) / 256, 3), 256>>>(
        (const float4*)Wq, (const float4*)Wk, (const float4*)Wv, NW4);
    cvt_wo<<<(NW4 + 255) / 256, 256>>>((const float4*)Wo, NW4);

    cudaFuncSetAttribute(gemm_qkv, cudaFuncAttributeMaxDynamicSharedMemorySize, GEMM16_SMEM);
    cudaFuncSetAttribute(gemm_out, cudaFuncAttributeMaxDynamicSharedMemorySize, GEMMO_SMEM);
    dim3 gq(DMODEL / 128, MROWS / 128, 3);
    gemm_qkv<<<gq, 256, GEMM16_SMEM>>>(xh16, xl16);

    cudaFuncSetAttribute(attn_mma, cudaFuncAttributeMaxDynamicSharedMemorySize, ATTN_SMEM);
    attn_mma<<<dim3(SEQ / 128, BATCH * HEADS), 256, ATTN_SMEM>>>();

    dim3 gg(DMODEL / 128, MROWS / 128);
    gemm_out<<<gg, 256, GEMMO_SMEM>>>(ahi, alo, (float*)d_out, bo);
}